// round 1
// baseline (speedup 1.0000x reference)
#include <cuda_runtime.h>
#include <cstdint>

#define B_SZ 8192
#define D_SZ 256
#define NCLS 512
#define MAXM 128
#define TM 64          // 8192 / 128 tiles per dimension
#define MARGIN 1.0f
#define BIGF 1e9f

// ---------------- device scratch (no allocations allowed) ----------------
__device__ float        g_e[B_SZ * D_SZ];        // normalized embeddings (8 MB)
__device__ unsigned int g_hn_bits[B_SZ];         // hardest-negative distance (float bits)
__device__ int          g_cls_cnt[NCLS];
__device__ int          g_cls_members[NCLS * MAXM];
__device__ float        g_total;
__device__ int          g_count;
__device__ int          g_lab64;                 // 1 if labels are int64-packed

// ---------------- label helpers ----------------
__device__ __forceinline__ int get_label(const int* l, int i, int is64) {
    return is64 ? l[2 * i] : l[i];
}

// Detect int64-packed labels: if every odd 32-bit word is zero, data is int64.
__global__ void detect_labels_k(const int* __restrict__ labels) {
    __shared__ int sh[256];
    int acc = 0;
    for (int i = threadIdx.x; i < B_SZ / 2; i += 256)
        acc |= labels[2 * i + 1];
    sh[threadIdx.x] = acc;
    __syncthreads();
    for (int o = 128; o; o >>= 1) {
        if (threadIdx.x < o) sh[threadIdx.x] |= sh[threadIdx.x + o];
        __syncthreads();
    }
    if (threadIdx.x == 0) g_lab64 = (sh[0] == 0) ? 1 : 0;
}

// ---------------- init (must reset every launch: graph replays) ----------------
__global__ void init_k() {
    int t = blockIdx.x * blockDim.x + threadIdx.x;
    if (t < B_SZ) g_hn_bits[t] = __float_as_uint(BIGF);
    if (t < NCLS) g_cls_cnt[t] = 0;
    if (t == 0) { g_total = 0.0f; g_count = 0; }
}

// ---------------- row L2-normalize ----------------
__global__ void normalize_k(const float* __restrict__ x) {
    int row = blockIdx.x;
    const float4* xr = (const float4*)(x + row * D_SZ);
    float4 v = xr[threadIdx.x];                      // 64 threads * float4 = 256
    float s = v.x * v.x + v.y * v.y + v.z * v.z + v.w * v.w;
    for (int o = 16; o; o >>= 1) s += __shfl_down_sync(0xFFFFFFFFu, s, o);
    __shared__ float ws[2];
    if ((threadIdx.x & 31) == 0) ws[threadIdx.x >> 5] = s;
    __syncthreads();
    float inv = 1.0f / fmaxf(sqrtf(ws[0] + ws[1]), 1e-12f);
    float4 o4 = make_float4(v.x * inv, v.y * inv, v.z * inv, v.w * inv);
    ((float4*)(g_e + row * D_SZ))[threadIdx.x] = o4;
}

// ---------------- fused GEMM + masked min (triangular grid) ----------------
// Tile 128x128, BK=16, 256 threads (16x16), 8x8 micro-tile (split 4+4).
__global__ __launch_bounds__(256) void min_gemm_k(const int* __restrict__ labels) {
    // map linear block id -> upper-triangular (bi, bj), bj >= bi
    int bid = blockIdx.x;
    int bi = 0;
    // f(bi) = blocks before row bi = bi*(2*TM - bi + 1)/2
    while (((bi + 1) * (2 * TM - bi)) / 2 <= bid) bi++;
    int bj = bi + (bid - (bi * (2 * TM - bi + 1)) / 2);

    int ib = bi * 128, jb = bj * 128;
    int tid = threadIdx.x;
    int tx = tid & 15, ty = tid >> 4;
    int is64 = g_lab64;

    __shared__ float As[16][128];
    __shared__ float Bs[16][128];
    __shared__ int   labA[128], labB[128];
    __shared__ float red[128][16];

    if (tid < 128)       labA[tid]        = get_label(labels, ib + tid, is64);
    else                 labB[tid - 128]  = get_label(labels, jb + (tid - 128), is64);

    float acc[8][8];
#pragma unroll
    for (int i = 0; i < 8; i++)
#pragma unroll
        for (int j = 0; j < 8; j++) acc[i][j] = 0.0f;

    for (int k0 = 0; k0 < D_SZ; k0 += 16) {
        // cooperative load: 128 rows x 16 cols for A and B (512 float4 each)
#pragma unroll
        for (int l = 0; l < 2; l++) {
            int idx = tid * 2 + l;              // 0..511
            int row = idx >> 2, q = idx & 3;    // q: which float4 in the 16-col strip
            float4 va = *(const float4*)(g_e + (size_t)(ib + row) * D_SZ + k0 + q * 4);
            As[q * 4 + 0][row] = va.x; As[q * 4 + 1][row] = va.y;
            As[q * 4 + 2][row] = va.z; As[q * 4 + 3][row] = va.w;
            float4 vb = *(const float4*)(g_e + (size_t)(jb + row) * D_SZ + k0 + q * 4);
            Bs[q * 4 + 0][row] = vb.x; Bs[q * 4 + 1][row] = vb.y;
            Bs[q * 4 + 2][row] = vb.z; Bs[q * 4 + 3][row] = vb.w;
        }
        __syncthreads();

#pragma unroll
        for (int kk = 0; kk < 16; kk++) {
            float4 a0 = *(const float4*)&As[kk][ty * 4];
            float4 a1 = *(const float4*)&As[kk][64 + ty * 4];
            float4 b0 = *(const float4*)&Bs[kk][tx * 4];
            float4 b1 = *(const float4*)&Bs[kk][64 + tx * 4];
            float a[8] = {a0.x, a0.y, a0.z, a0.w, a1.x, a1.y, a1.z, a1.w};
            float b[8] = {b0.x, b0.y, b0.z, b0.w, b1.x, b1.y, b1.z, b1.w};
#pragma unroll
            for (int i = 0; i < 8; i++)
#pragma unroll
                for (int j = 0; j < 8; j++) acc[i][j] = fmaf(a[i], b[j], acc[i][j]);
        }
        __syncthreads();
    }

    // distances + label mask, per-thread row/col mins
    int ir[8], jc[8];
#pragma unroll
    for (int i = 0; i < 8; i++) ir[i] = (i < 4) ? (ty * 4 + i) : (64 + ty * 4 + i - 4);
#pragma unroll
    for (int j = 0; j < 8; j++) jc[j] = (j < 4) ? (tx * 4 + j) : (64 + tx * 4 + j - 4);

    float rmin[8], cmin[8];
#pragma unroll
    for (int i = 0; i < 8; i++) rmin[i] = BIGF;
#pragma unroll
    for (int j = 0; j < 8; j++) cmin[j] = BIGF;

#pragma unroll
    for (int i = 0; i < 8; i++) {
        int la = labA[ir[i]];
#pragma unroll
        for (int j = 0; j < 8; j++) {
            float d = fmaxf(1.0f - acc[i][j], 0.0f);
            float cand = (la != labB[jc[j]]) ? d : BIGF;
            rmin[i] = fminf(rmin[i], cand);
            cmin[j] = fminf(cmin[j], cand);
        }
    }

    // block reduce rows
#pragma unroll
    for (int i = 0; i < 8; i++) red[ir[i]][tx] = rmin[i];
    __syncthreads();
    if (tid < 128) {
        float m = red[tid][0];
#pragma unroll
        for (int t = 1; t < 16; t++) m = fminf(m, red[tid][t]);
        if (m < BIGF) atomicMin(&g_hn_bits[ib + tid], __float_as_uint(m));
    }
    __syncthreads();
    // block reduce cols (symmetry: d_ji = d_ij)
#pragma unroll
    for (int j = 0; j < 8; j++) red[jc[j]][ty] = cmin[j];
    __syncthreads();
    if (tid < 128) {
        float m = red[tid][0];
#pragma unroll
        for (int t = 1; t < 16; t++) m = fminf(m, red[tid][t]);
        if (m < BIGF) atomicMin(&g_hn_bits[jb + tid], __float_as_uint(m));
    }
}

// ---------------- bucket rows by class ----------------
__global__ void build_lists_k(const int* __restrict__ labels) {
    int i = blockIdx.x * blockDim.x + threadIdx.x;
    if (i >= B_SZ) return;
    int c = get_label(labels, i, g_lab64);
    int p = atomicAdd(&g_cls_cnt[c], 1);
    if (p < MAXM) g_cls_members[c * MAXM + p] = i;
}

// ---------------- positive-pair losses (within class only) ----------------
__global__ __launch_bounds__(256) void class_loss_k() {
    int c = blockIdx.x;
    int m = min(g_cls_cnt[c], MAXM);
    float lt = 0.0f; int lc = 0;
    for (int p = threadIdx.x; p < m * m; p += 256) {
        int a = p / m, b = p % m;
        if (a == b) continue;
        int ia = g_cls_members[c * MAXM + a];
        int ib = g_cls_members[c * MAXM + b];
        const float4* ea = (const float4*)(g_e + (size_t)ia * D_SZ);
        const float4* eb = (const float4*)(g_e + (size_t)ib * D_SZ);
        float s = 0.0f;
#pragma unroll 16
        for (int q = 0; q < D_SZ / 4; q++) {
            float4 va = ea[q], vb = eb[q];
            s = fmaf(va.x, vb.x, s); s = fmaf(va.y, vb.y, s);
            s = fmaf(va.z, vb.z, s); s = fmaf(va.w, vb.w, s);
        }
        float d = fmaxf(1.0f - s, 0.0f);
        float hn = __uint_as_float(g_hn_bits[ia]);
        float loss = d - hn + MARGIN;
        if (loss > 0.0f) { lt += loss; lc++; }
    }
    __shared__ float st[256];
    __shared__ int   sc[256];
    st[threadIdx.x] = lt; sc[threadIdx.x] = lc;
    __syncthreads();
    for (int o = 128; o; o >>= 1) {
        if (threadIdx.x < o) {
            st[threadIdx.x] += st[threadIdx.x + o];
            sc[threadIdx.x] += sc[threadIdx.x + o];
        }
        __syncthreads();
    }
    if (threadIdx.x == 0 && sc[0] > 0) {
        atomicAdd(&g_total, st[0]);
        atomicAdd(&g_count, sc[0]);
    }
}

__global__ void finalize_k(float* out) {
    if (threadIdx.x == 0)
        out[0] = (g_count > 0) ? (g_total / (float)g_count) : 0.0f;
}

// ---------------- launch ----------------
extern "C" void kernel_launch(void* const* d_in, const int* in_sizes, int n_in,
                              void* d_out, int out_size) {
    const float* emb = (const float*)d_in[0];
    const int* labels = (const int*)d_in[1];   // int32 or int64-packed, detected on device
    float* out = (float*)d_out;
    (void)in_sizes; (void)n_in; (void)out_size;

    detect_labels_k<<<1, 256>>>(labels);
    init_k<<<(B_SZ + 255) / 256, 256>>>();
    normalize_k<<<B_SZ, 64>>>(emb);
    min_gemm_k<<<TM * (TM + 1) / 2, 256>>>(labels);
    build_lists_k<<<(B_SZ + 255) / 256, 256>>>(labels);
    class_loss_k<<<NCLS, 256>>>();
    finalize_k<<<1, 32>>>(out);
}

// round 3
// speedup vs baseline: 1.4739x; 1.4739x over previous
#include <cuda_runtime.h>
#include <cuda_fp16.h>
#include <cstdint>

#define B_SZ 8192
#define D_SZ 256
#define NCLS 512
#define MAXM 128
#define TM 64          // 8192/128 tiles per dim
#define MARGIN 1.0f
#define BIGF 1e9f

#define TILE_BYTES 16384                 // 128 rows * 128B (64 fp16)
#define SMEM_DYN (4 * TILE_BYTES + 1024)

// ---------------- device scratch ----------------
__device__ float        g_e[B_SZ * D_SZ];     // normalized fp32 (pass 2)
__device__ __half       g_hi[B_SZ * D_SZ];    // fp16 high part
__device__ __half       g_lo[B_SZ * D_SZ];    // fp16 residual
__device__ unsigned int g_hn_bits[B_SZ];
__device__ int          g_cls_cnt[NCLS];
__device__ int          g_cls_members[NCLS * MAXM];
__device__ float        g_total;
__device__ int          g_count;
__device__ int          g_lab64;

// ---------------- helpers ----------------
__device__ __forceinline__ uint32_t smem_u32(const void* p) {
    uint32_t a;
    asm("{ .reg .u64 t; cvta.to.shared.u64 t, %1; cvt.u32.u64 %0, t; }" : "=r"(a) : "l"(p));
    return a;
}
__device__ __forceinline__ int get_label(const int* l, int i, int is64) {
    return is64 ? l[2 * i] : l[i];
}

#define LDSM4(r0, r1, r2, r3, addr)                                          \
    asm volatile("ldmatrix.sync.aligned.m8n8.x4.shared.b16 {%0,%1,%2,%3}, [%4];" \
                 : "=r"(r0), "=r"(r1), "=r"(r2), "=r"(r3) : "r"(addr))

#define MMA16816(d, a0, a1, a2, a3, b0, b1)                                  \
    asm volatile("mma.sync.aligned.m16n8k16.row.col.f32.f16.f16.f32 "        \
                 "{%0,%1,%2,%3}, {%4,%5,%6,%7}, {%8,%9}, {%0,%1,%2,%3};"     \
                 : "+f"(d[0]), "+f"(d[1]), "+f"(d[2]), "+f"(d[3])            \
                 : "r"(a0), "r"(a1), "r"(a2), "r"(a3), "r"(b0), "r"(b1))

// ---------------- label dtype sniff ----------------
__global__ void detect_labels_k(const int* __restrict__ labels) {
    __shared__ int sh[256];
    int acc = 0;
    for (int i = threadIdx.x; i < B_SZ / 2; i += 256) acc |= labels[2 * i + 1];
    sh[threadIdx.x] = acc;
    __syncthreads();
    for (int o = 128; o; o >>= 1) {
        if (threadIdx.x < o) sh[threadIdx.x] |= sh[threadIdx.x + o];
        __syncthreads();
    }
    if (threadIdx.x == 0) g_lab64 = (sh[0] == 0) ? 1 : 0;
}

// ---------------- per-launch reset ----------------
__global__ void init_k() {
    int t = blockIdx.x * blockDim.x + threadIdx.x;
    if (t < B_SZ) g_hn_bits[t] = __float_as_uint(BIGF);
    if (t < NCLS) g_cls_cnt[t] = 0;
    if (t == 0) { g_total = 0.0f; g_count = 0; }
}

// ---------------- normalize + fp16 hi/lo split ----------------
__global__ void normalize_k(const float* __restrict__ x) {
    int row = blockIdx.x;
    const float4* xr = (const float4*)(x + (size_t)row * D_SZ);
    float4 v = xr[threadIdx.x];                 // 64 threads * float4
    float s = v.x * v.x + v.y * v.y + v.z * v.z + v.w * v.w;
    for (int o = 16; o; o >>= 1) s += __shfl_down_sync(0xFFFFFFFFu, s, o);
    __shared__ float ws[2];
    if ((threadIdx.x & 31) == 0) ws[threadIdx.x >> 5] = s;
    __syncthreads();
    float inv = 1.0f / fmaxf(sqrtf(ws[0] + ws[1]), 1e-12f);
    float e[4] = {v.x * inv, v.y * inv, v.z * inv, v.w * inv};
    ((float4*)(g_e + (size_t)row * D_SZ))[threadIdx.x] = make_float4(e[0], e[1], e[2], e[3]);
    size_t base = (size_t)row * D_SZ + threadIdx.x * 4;
#pragma unroll
    for (int q = 0; q < 4; q++) {
        __half h = __float2half_rn(e[q]);
        float r = e[q] - __half2float(h);
        g_hi[base + q] = h;
        g_lo[base + q] = __float2half_rn(r);
    }
}

// ---------------- HMMA GEMM + masked min, triangular grid ----------------
// 256 threads = 8 warps (2x4). Warp computes 64x32. K in 4 chunks of 64.
// dot = Ah*Bh' + Ah*Bl' + Al*Bh' (fp32 accum) — ~2^-22 rel err.
__global__ __launch_bounds__(256, 2) void min_gemm_hmma(const int* __restrict__ labels) {
    extern __shared__ char dyn[];
    __shared__ int   labA[128], labB[128];
    __shared__ float s_rmin[128][4];
    __shared__ float s_cmin[128][2];

    int bid = blockIdx.x;
    int bi = 0;
    while (((bi + 1) * (2 * TM - bi)) / 2 <= bid) bi++;
    int bj = bi + (bid - (bi * (2 * TM - bi + 1)) / 2);
    int ib = bi * 128, jb = bj * 128;

    int tid = threadIdx.x;
    int lane = tid & 31, wid = tid >> 5;
    int wr = wid >> 2, wc = wid & 3;           // warp grid 2x4
    int rbase = wr * 64, cbase = wc * 32;
    int is64 = g_lab64;

    // 1024-aligned tile region
    uint32_t dbase = smem_u32(dyn);
    uint32_t tb = (dbase + 1023u) & ~1023u;
    char* tilesc = dyn + (tb - dbase);
    uint32_t tile_u[4];                        // Ah, Al, Bh, Bl
#pragma unroll
    for (int t = 0; t < 4; t++) tile_u[t] = tb + t * TILE_BYTES;

    if (tid < 128) labA[tid] = get_label(labels, ib + tid, is64);
    else           labB[tid - 128] = get_label(labels, jb + (tid - 128), is64);

    float acc[4][4][4];
#pragma unroll
    for (int mf = 0; mf < 4; mf++)
#pragma unroll
        for (int nf = 0; nf < 4; nf++)
#pragma unroll
            for (int r = 0; r < 4; r++) acc[mf][nf][r] = 0.0f;

    // per-lane ldmatrix addressing
    int a_row = lane & 15;
    int a_kb  = (lane >> 4) * 16;              // k byte offset (8 halves)
    uint32_t a_xor = (uint32_t)(a_row & 7) << 4;
    int b_n  = (lane & 7) + ((lane >> 4) << 3);
    int b_kb = ((lane >> 3) & 1) * 16;
    uint32_t b_xor = (uint32_t)(b_n & 7) << 4;

    const int termA[3] = {0, 0, 1};            // Ah, Ah, Al
    const int termB[3] = {2, 3, 2};            // Bh, Bl, Bh

    for (int chunk = 0; chunk < 4; chunk++) {
        __syncthreads();
        // load 4 tiles: 128 rows x 128B each, XOR-swizzled
#pragma unroll
        for (int r = 0; r < 4; r++) {
            int idx = tid + 256 * r;           // 0..1023
            int row = idx >> 3, seg = idx & 7;
            size_t gofs = (size_t)row * 512 + (size_t)chunk * 128 + (size_t)seg * 16;
            uint32_t off = (uint32_t)(row * 128 + ((seg * 16) ^ ((row & 7) << 4)));
            *(uint4*)(tilesc + 0 * TILE_BYTES + off) =
                *(const uint4*)((const char*)g_hi + (size_t)ib * 512 + gofs);
            *(uint4*)(tilesc + 1 * TILE_BYTES + off) =
                *(const uint4*)((const char*)g_lo + (size_t)ib * 512 + gofs);
            *(uint4*)(tilesc + 2 * TILE_BYTES + off) =
                *(const uint4*)((const char*)g_hi + (size_t)jb * 512 + gofs);
            *(uint4*)(tilesc + 3 * TILE_BYTES + off) =
                *(const uint4*)((const char*)g_lo + (size_t)jb * 512 + gofs);
        }
        __syncthreads();

#pragma unroll
        for (int term = 0; term < 3; term++) {
            uint32_t aBase  = tile_u[termA[term]] + (uint32_t)(rbase + a_row) * 128;
            uint32_t bBase0 = tile_u[termB[term]] + (uint32_t)(cbase + b_n) * 128;
            uint32_t bBase1 = bBase0 + 16 * 128;
#pragma unroll
            for (int ks = 0; ks < 4; ks++) {
                uint32_t kA = ((uint32_t)(ks * 32 + a_kb)) ^ a_xor;
                uint32_t kB = ((uint32_t)(ks * 32 + b_kb)) ^ b_xor;
                uint32_t b0, b1, b2, b3, b4, b5, b6, b7;
                LDSM4(b0, b1, b2, b3, bBase0 + kB);
                LDSM4(b4, b5, b6, b7, bBase1 + kB);
#pragma unroll
                for (int mf = 0; mf < 4; mf++) {
                    uint32_t a0, a1, a2, a3;
                    LDSM4(a0, a1, a2, a3, aBase + mf * 2048 + kA);
                    MMA16816(acc[mf][0], a0, a1, a2, a3, b0, b1);
                    MMA16816(acc[mf][1], a0, a1, a2, a3, b2, b3);
                    MMA16816(acc[mf][2], a0, a1, a2, a3, b4, b5);
                    MMA16816(acc[mf][3], a0, a1, a2, a3, b6, b7);
                }
            }
        }
    }

    // ---------------- epilogue: mask + min in registers ----------------
    int qr = lane >> 2, qc = lane & 3;
    float rmin[8], cmin[8];
#pragma unroll
    for (int i = 0; i < 8; i++) { rmin[i] = BIGF; cmin[i] = BIGF; }

#pragma unroll
    for (int mf = 0; mf < 4; mf++) {
        int la0 = labA[rbase + mf * 16 + qr];
        int la1 = labA[rbase + mf * 16 + qr + 8];
#pragma unroll
        for (int nf = 0; nf < 4; nf++) {
            int c0 = cbase + nf * 8 + qc * 2;
            int lb0 = labB[c0], lb1 = labB[c0 + 1];
            float d0 = fmaxf(1.0f - acc[mf][nf][0], 0.0f);
            float d1 = fmaxf(1.0f - acc[mf][nf][1], 0.0f);
            float d2 = fmaxf(1.0f - acc[mf][nf][2], 0.0f);
            float d3 = fmaxf(1.0f - acc[mf][nf][3], 0.0f);
            float v0 = (la0 != lb0) ? d0 : BIGF;
            float v1 = (la0 != lb1) ? d1 : BIGF;
            float v2 = (la1 != lb0) ? d2 : BIGF;
            float v3 = (la1 != lb1) ? d3 : BIGF;
            rmin[mf * 2 + 0] = fminf(rmin[mf * 2 + 0], fminf(v0, v1));
            rmin[mf * 2 + 1] = fminf(rmin[mf * 2 + 1], fminf(v2, v3));
            cmin[nf * 2 + 0] = fminf(cmin[nf * 2 + 0], fminf(v0, v2));
            cmin[nf * 2 + 1] = fminf(cmin[nf * 2 + 1], fminf(v1, v3));
        }
    }
    // row-min across quad (lanes sharing qr)
#pragma unroll
    for (int o = 1; o <= 2; o <<= 1)
#pragma unroll
        for (int i = 0; i < 8; i++)
            rmin[i] = fminf(rmin[i], __shfl_xor_sync(0xFFFFFFFFu, rmin[i], o));
    if (qc == 0) {
#pragma unroll
        for (int mf = 0; mf < 4; mf++) {
            s_rmin[rbase + mf * 16 + qr + 0][wc] = rmin[mf * 2 + 0];
            s_rmin[rbase + mf * 16 + qr + 8][wc] = rmin[mf * 2 + 1];
        }
    }
    // col-min across qr groups (lanes sharing qc)
#pragma unroll
    for (int o = 4; o <= 16; o <<= 1)
#pragma unroll
        for (int i = 0; i < 8; i++)
            cmin[i] = fminf(cmin[i], __shfl_xor_sync(0xFFFFFFFFu, cmin[i], o));
    if (lane < 4) {
#pragma unroll
        for (int nf = 0; nf < 4; nf++) {
            s_cmin[cbase + nf * 8 + lane * 2 + 0][wr] = cmin[nf * 2 + 0];
            s_cmin[cbase + nf * 8 + lane * 2 + 1][wr] = cmin[nf * 2 + 1];
        }
    }
    __syncthreads();
    if (tid < 128) {
        float m = fminf(fminf(s_rmin[tid][0], s_rmin[tid][1]),
                        fminf(s_rmin[tid][2], s_rmin[tid][3]));
        if (m < BIGF) atomicMin(&g_hn_bits[ib + tid], __float_as_uint(m));
        float c = fminf(s_cmin[tid][0], s_cmin[tid][1]);
        if (c < BIGF) atomicMin(&g_hn_bits[jb + tid], __float_as_uint(c)); // symmetry
    }
}

// ---------------- bucket rows by class ----------------
__global__ void build_lists_k(const int* __restrict__ labels) {
    int i = blockIdx.x * blockDim.x + threadIdx.x;
    if (i >= B_SZ) return;
    int c = get_label(labels, i, g_lab64);
    int p = atomicAdd(&g_cls_cnt[c], 1);
    if (p < MAXM) g_cls_members[c * MAXM + p] = i;
}

// ---------------- positive-pair losses (within class, fp32) ----------------
__global__ __launch_bounds__(256) void class_loss_k() {
    int c = blockIdx.x;
    int m = min(g_cls_cnt[c], MAXM);
    float lt = 0.0f; int lc = 0;
    for (int p = threadIdx.x; p < m * m; p += 256) {
        int a = p / m, b = p % m;
        if (a == b) continue;
        int ia = g_cls_members[c * MAXM + a];
        int ib = g_cls_members[c * MAXM + b];
        const float4* ea = (const float4*)(g_e + (size_t)ia * D_SZ);
        const float4* eb = (const float4*)(g_e + (size_t)ib * D_SZ);
        float s = 0.0f;
#pragma unroll 16
        for (int q = 0; q < D_SZ / 4; q++) {
            float4 va = ea[q], vb = eb[q];
            s = fmaf(va.x, vb.x, s); s = fmaf(va.y, vb.y, s);
            s = fmaf(va.z, vb.z, s); s = fmaf(va.w, vb.w, s);
        }
        float d = fmaxf(1.0f - s, 0.0f);
        float hn = __uint_as_float(g_hn_bits[ia]);
        float loss = d - hn + MARGIN;
        if (loss > 0.0f) { lt += loss; lc++; }
    }
    __shared__ float st[256];
    __shared__ int   sc[256];
    st[threadIdx.x] = lt; sc[threadIdx.x] = lc;
    __syncthreads();
    for (int o = 128; o; o >>= 1) {
        if (threadIdx.x < o) {
            st[threadIdx.x] += st[threadIdx.x + o];
            sc[threadIdx.x] += sc[threadIdx.x + o];
        }
        __syncthreads();
    }
    if (threadIdx.x == 0 && sc[0] > 0) {
        atomicAdd(&g_total, st[0]);
        atomicAdd(&g_count, sc[0]);
    }
}

__global__ void finalize_k(float* out) {
    if (threadIdx.x == 0)
        out[0] = (g_count > 0) ? (g_total / (float)g_count) : 0.0f;
}

// ---------------- launch ----------------
extern "C" void kernel_launch(void* const* d_in, const int* in_sizes, int n_in,
                              void* d_out, int out_size) {
    const float* emb = (const float*)d_in[0];
    const int* labels = (const int*)d_in[1];
    float* out = (float*)d_out;
    (void)in_sizes; (void)n_in; (void)out_size;

    static int smem_set = 0;
    if (!smem_set) {
        cudaFuncSetAttribute(min_gemm_hmma,
                             cudaFuncAttributeMaxDynamicSharedMemorySize, SMEM_DYN);
        smem_set = 1;
    }

    detect_labels_k<<<1, 256>>>(labels);
    init_k<<<(B_SZ + 255) / 256, 256>>>();
    normalize_k<<<B_SZ, 64>>>(emb);
    min_gemm_hmma<<<TM * (TM + 1) / 2, 256, SMEM_DYN>>>(labels);
    build_lists_k<<<(B_SZ + 255) / 256, 256>>>(labels);
    class_loss_k<<<NCLS, 256>>>();
    finalize_k<<<1, 32>>>(out);
}

// round 4
// speedup vs baseline: 2.1999x; 1.4925x over previous
#include <cuda_runtime.h>
#include <cuda_fp16.h>
#include <cstdint>

#define B_SZ 8192
#define D_SZ 256
#define NCLS 512
#define MAXM 128
#define TM 64
#define MARGIN 1.0f
#define BIGF 1e9f

#define TILE_BYTES 16384                   // 128 rows * 128B
#define STAGE_BYTES (4 * TILE_BYTES)       // Ah, Al, Bh, Bl
#define SMEM_DYN (2 * STAGE_BYTES + 1024)  // double-buffered + align slack
#define CLS_CH 32
#define CLS_SMEM (2 * CLS_CH * D_SZ * 4)   // 64KB

// ---------------- device scratch ----------------
__device__ float        g_e[B_SZ * D_SZ];
__device__ __half       g_hi[B_SZ * D_SZ];
__device__ __half       g_lo[B_SZ * D_SZ];
__device__ unsigned int g_hn_bits[B_SZ];
__device__ int          g_cls_cnt[NCLS];
__device__ int          g_cls_members[NCLS * MAXM];
__device__ float        g_total;
__device__ int          g_count;
__device__ int          g_lab64;

// ---------------- helpers ----------------
__device__ __forceinline__ uint32_t smem_u32(const void* p) {
    uint32_t a;
    asm("{ .reg .u64 t; cvta.to.shared.u64 t, %1; cvt.u32.u64 %0, t; }" : "=r"(a) : "l"(p));
    return a;
}
__device__ __forceinline__ int get_label(const int* l, int i, int is64) {
    return is64 ? l[2 * i] : l[i];
}

#define LDSM4(r0, r1, r2, r3, addr)                                              \
    asm volatile("ldmatrix.sync.aligned.m8n8.x4.shared.b16 {%0,%1,%2,%3}, [%4];" \
                 : "=r"(r0), "=r"(r1), "=r"(r2), "=r"(r3) : "r"(addr))

#define MMA16816(d, a0, a1, a2, a3, b0, b1)                                  \
    asm volatile("mma.sync.aligned.m16n8k16.row.col.f32.f16.f16.f32 "        \
                 "{%0,%1,%2,%3}, {%4,%5,%6,%7}, {%8,%9}, {%0,%1,%2,%3};"     \
                 : "+f"(d[0]), "+f"(d[1]), "+f"(d[2]), "+f"(d[3])            \
                 : "r"(a0), "r"(a1), "r"(a2), "r"(a3), "r"(b0), "r"(b1))

#define CPA16(dst, src)                                                       \
    asm volatile("cp.async.cg.shared.global [%0], [%1], 16;"                  \
                 :: "r"(dst), "l"(src) : "memory")
#define CPA_COMMIT asm volatile("cp.async.commit_group;" ::: "memory")
#define CPA_WAIT(n) asm volatile("cp.async.wait_group %0;" :: "n"(n) : "memory")

// ---------------- pre: detect label dtype + reset state ----------------
__global__ void pre_k(const int* __restrict__ labels) {
    if (blockIdx.x == 0) {
        __shared__ int sh[256];
        int acc = 0;
        for (int i = threadIdx.x; i < B_SZ / 2; i += 256) acc |= labels[2 * i + 1];
        sh[threadIdx.x] = acc;
        __syncthreads();
        for (int o = 128; o; o >>= 1) {
            if (threadIdx.x < o) sh[threadIdx.x] |= sh[threadIdx.x + o];
            __syncthreads();
        }
        if (threadIdx.x == 0) g_lab64 = (sh[0] == 0) ? 1 : 0;
    } else {
        int t = (blockIdx.x - 1) * 256 + threadIdx.x;
        if (t < B_SZ) g_hn_bits[t] = __float_as_uint(BIGF);
        if (t < NCLS) g_cls_cnt[t] = 0;
        if (t == 0) { g_total = 0.0f; g_count = 0; }
    }
}

// ---------------- normalize (warp/row) + fp16 split + class bucketing ----------------
__global__ __launch_bounds__(256) void normalize_k(const float* __restrict__ x,
                                                   const int* __restrict__ labels) {
    int wid = threadIdx.x >> 5, lane = threadIdx.x & 31;
    int row = blockIdx.x * 8 + wid;
    size_t base = (size_t)row * D_SZ + lane * 8;
    float4 v0 = *(const float4*)(x + base);
    float4 v1 = *(const float4*)(x + base + 4);
    float e[8] = {v0.x, v0.y, v0.z, v0.w, v1.x, v1.y, v1.z, v1.w};
    float s = 0.0f;
#pragma unroll
    for (int q = 0; q < 8; q++) s += e[q] * e[q];
#pragma unroll
    for (int o = 16; o; o >>= 1) s += __shfl_xor_sync(0xFFFFFFFFu, s, o);
    float inv = 1.0f / fmaxf(sqrtf(s), 1e-12f);

    union { __half h[8]; uint4 u; } hi, lo;
#pragma unroll
    for (int q = 0; q < 8; q++) {
        e[q] *= inv;
        __half h = __float2half_rn(e[q]);
        hi.h[q] = h;
        lo.h[q] = __float2half_rn(e[q] - __half2float(h));
    }
    *(float4*)(g_e + base)     = make_float4(e[0], e[1], e[2], e[3]);
    *(float4*)(g_e + base + 4) = make_float4(e[4], e[5], e[6], e[7]);
    *(uint4*)(g_hi + base) = hi.u;
    *(uint4*)(g_lo + base) = lo.u;

    if (lane == 0) {  // class bucketing, one entry per row
        int c = get_label(labels, row, g_lab64);
        int p = atomicAdd(&g_cls_cnt[c], 1);
        if (p < MAXM) g_cls_members[c * MAXM + p] = row;
    }
}

// ---------------- HMMA GEMM + masked min: cp.async double-buffered ----------------
__device__ __forceinline__ void issue_chunk(uint32_t sbase, int chunk, int ib, int jb,
                                            int tid) {
#pragma unroll
    for (int r = 0; r < 4; r++) {
        int idx = tid + 256 * r;             // 0..1023
        int row = idx >> 3, seg = idx & 7;
        size_t gofs = (size_t)row * 512 + (size_t)chunk * 128 + (size_t)seg * 16;
        uint32_t off = (uint32_t)(row * 128 + ((seg * 16) ^ ((row & 7) << 4)));
        CPA16(sbase + 0 * TILE_BYTES + off, (const char*)g_hi + (size_t)ib * 512 + gofs);
        CPA16(sbase + 1 * TILE_BYTES + off, (const char*)g_lo + (size_t)ib * 512 + gofs);
        CPA16(sbase + 2 * TILE_BYTES + off, (const char*)g_hi + (size_t)jb * 512 + gofs);
        CPA16(sbase + 3 * TILE_BYTES + off, (const char*)g_lo + (size_t)jb * 512 + gofs);
    }
    CPA_COMMIT;
}

__global__ __launch_bounds__(256, 1) void min_gemm_hmma(const int* __restrict__ labels) {
    extern __shared__ char dyn[];
    __shared__ int   labA[128], labB[128];
    __shared__ float s_rmin[128][4];
    __shared__ float s_cmin[128][2];

    int bid = blockIdx.x;
    int bi = 0;
    while (((bi + 1) * (2 * TM - bi)) / 2 <= bid) bi++;
    int bj = bi + (bid - (bi * (2 * TM - bi + 1)) / 2);
    int ib = bi * 128, jb = bj * 128;

    int tid = threadIdx.x;
    int lane = tid & 31, wid = tid >> 5;
    int wr = wid >> 2, wc = wid & 3;
    int rbase = wr * 64, cbase = wc * 32;
    int is64 = g_lab64;

    uint32_t dbase = smem_u32(dyn);
    uint32_t tb = (dbase + 1023u) & ~1023u;

    if (tid < 128) labA[tid] = get_label(labels, ib + tid, is64);
    else           labB[tid - 128] = get_label(labels, jb + (tid - 128), is64);

    // prologue: stage 0 in flight
    issue_chunk(tb, 0, ib, jb, tid);

    float acc[4][4][4];
#pragma unroll
    for (int mf = 0; mf < 4; mf++)
#pragma unroll
        for (int nf = 0; nf < 4; nf++)
#pragma unroll
            for (int r = 0; r < 4; r++) acc[mf][nf][r] = 0.0f;

    int a_row = lane & 15;
    int a_kb  = (lane >> 4) * 16;
    uint32_t a_xor = (uint32_t)(a_row & 7) << 4;
    int b_n  = (lane & 7) + ((lane >> 4) << 3);
    int b_kb = ((lane >> 3) & 1) * 16;
    uint32_t b_xor = (uint32_t)(b_n & 7) << 4;
    uint32_t aOff = (uint32_t)(rbase + a_row) * 128;
    uint32_t bOff0 = (uint32_t)(cbase + b_n) * 128;
    uint32_t bOff1 = bOff0 + 16 * 128;

    for (int chunk = 0; chunk < 4; chunk++) {
        if (chunk < 3) {
            issue_chunk(tb + ((chunk + 1) & 1) * STAGE_BYTES, chunk + 1, ib, jb, tid);
            CPA_WAIT(1);
        } else {
            CPA_WAIT(0);
        }
        __syncthreads();

        uint32_t base = tb + (chunk & 1) * STAGE_BYTES;
        uint32_t tAh = base, tAl = base + TILE_BYTES;
        uint32_t tBh = base + 2 * TILE_BYTES, tBl = base + 3 * TILE_BYTES;

#pragma unroll
        for (int ks = 0; ks < 4; ks++) {
            uint32_t kA = ((uint32_t)(ks * 32 + a_kb)) ^ a_xor;
            uint32_t kB = ((uint32_t)(ks * 32 + b_kb)) ^ b_xor;
            uint32_t bh[8], bl[8];
            LDSM4(bh[0], bh[1], bh[2], bh[3], tBh + bOff0 + kB);
            LDSM4(bh[4], bh[5], bh[6], bh[7], tBh + bOff1 + kB);
            LDSM4(bl[0], bl[1], bl[2], bl[3], tBl + bOff0 + kB);
            LDSM4(bl[4], bl[5], bl[6], bl[7], tBl + bOff1 + kB);
#pragma unroll
            for (int mf = 0; mf < 4; mf++) {
                uint32_t ah0, ah1, ah2, ah3, al0, al1, al2, al3;
                LDSM4(ah0, ah1, ah2, ah3, tAh + aOff + mf * 2048 + kA);
                LDSM4(al0, al1, al2, al3, tAl + aOff + mf * 2048 + kA);
                // term Ah*Bh
                MMA16816(acc[mf][0], ah0, ah1, ah2, ah3, bh[0], bh[1]);
                MMA16816(acc[mf][1], ah0, ah1, ah2, ah3, bh[2], bh[3]);
                MMA16816(acc[mf][2], ah0, ah1, ah2, ah3, bh[4], bh[5]);
                MMA16816(acc[mf][3], ah0, ah1, ah2, ah3, bh[6], bh[7]);
                // term Ah*Bl
                MMA16816(acc[mf][0], ah0, ah1, ah2, ah3, bl[0], bl[1]);
                MMA16816(acc[mf][1], ah0, ah1, ah2, ah3, bl[2], bl[3]);
                MMA16816(acc[mf][2], ah0, ah1, ah2, ah3, bl[4], bl[5]);
                MMA16816(acc[mf][3], ah0, ah1, ah2, ah3, bl[6], bl[7]);
                // term Al*Bh
                MMA16816(acc[mf][0], al0, al1, al2, al3, bh[0], bh[1]);
                MMA16816(acc[mf][1], al0, al1, al2, al3, bh[2], bh[3]);
                MMA16816(acc[mf][2], al0, al1, al2, al3, bh[4], bh[5]);
                MMA16816(acc[mf][3], al0, al1, al2, al3, bh[6], bh[7]);
            }
        }
        __syncthreads();
    }

    // ---------------- epilogue: mask + min in registers ----------------
    int qr = lane >> 2, qc = lane & 3;
    float rmin[8], cmin[8];
#pragma unroll
    for (int i = 0; i < 8; i++) { rmin[i] = BIGF; cmin[i] = BIGF; }

#pragma unroll
    for (int mf = 0; mf < 4; mf++) {
        int la0 = labA[rbase + mf * 16 + qr];
        int la1 = labA[rbase + mf * 16 + qr + 8];
#pragma unroll
        for (int nf = 0; nf < 4; nf++) {
            int c0 = cbase + nf * 8 + qc * 2;
            int lb0 = labB[c0], lb1 = labB[c0 + 1];
            float d0 = fmaxf(1.0f - acc[mf][nf][0], 0.0f);
            float d1 = fmaxf(1.0f - acc[mf][nf][1], 0.0f);
            float d2 = fmaxf(1.0f - acc[mf][nf][2], 0.0f);
            float d3 = fmaxf(1.0f - acc[mf][nf][3], 0.0f);
            float v0 = (la0 != lb0) ? d0 : BIGF;
            float v1 = (la0 != lb1) ? d1 : BIGF;
            float v2 = (la1 != lb0) ? d2 : BIGF;
            float v3 = (la1 != lb1) ? d3 : BIGF;
            rmin[mf * 2 + 0] = fminf(rmin[mf * 2 + 0], fminf(v0, v1));
            rmin[mf * 2 + 1] = fminf(rmin[mf * 2 + 1], fminf(v2, v3));
            cmin[nf * 2 + 0] = fminf(cmin[nf * 2 + 0], fminf(v0, v2));
            cmin[nf * 2 + 1] = fminf(cmin[nf * 2 + 1], fminf(v1, v3));
        }
    }
#pragma unroll
    for (int o = 1; o <= 2; o <<= 1)
#pragma unroll
        for (int i = 0; i < 8; i++)
            rmin[i] = fminf(rmin[i], __shfl_xor_sync(0xFFFFFFFFu, rmin[i], o));
    if (qc == 0) {
#pragma unroll
        for (int mf = 0; mf < 4; mf++) {
            s_rmin[rbase + mf * 16 + qr + 0][wc] = rmin[mf * 2 + 0];
            s_rmin[rbase + mf * 16 + qr + 8][wc] = rmin[mf * 2 + 1];
        }
    }
#pragma unroll
    for (int o = 4; o <= 16; o <<= 1)
#pragma unroll
        for (int i = 0; i < 8; i++)
            cmin[i] = fminf(cmin[i], __shfl_xor_sync(0xFFFFFFFFu, cmin[i], o));
    if (lane < 4) {
#pragma unroll
        for (int nf = 0; nf < 4; nf++) {
            s_cmin[cbase + nf * 8 + lane * 2 + 0][wr] = cmin[nf * 2 + 0];
            s_cmin[cbase + nf * 8 + lane * 2 + 1][wr] = cmin[nf * 2 + 1];
        }
    }
    __syncthreads();
    if (tid < 128) {
        float m = fminf(fminf(s_rmin[tid][0], s_rmin[tid][1]),
                        fminf(s_rmin[tid][2], s_rmin[tid][3]));
        if (m < BIGF) atomicMin(&g_hn_bits[ib + tid], __float_as_uint(m));
        float c = fminf(s_cmin[tid][0], s_cmin[tid][1]);
        if (c < BIGF) atomicMin(&g_hn_bits[jb + tid], __float_as_uint(c));
    }
}

// ---------------- positive-pair losses: smem-cached class rows ----------------
__global__ __launch_bounds__(256) void class_loss_k() {
    extern __shared__ float cls[];
    float* sa = cls;
    float* sb = cls + CLS_CH * D_SZ;
    int c = blockIdx.x;
    int m = min(g_cls_cnt[c], MAXM);
    int tid = threadIdx.x;
    const int* mem = &g_cls_members[c * MAXM];
    float lt = 0.0f; int lc = 0;

    for (int a0 = 0; a0 < m; a0 += CLS_CH) {
        int na = min(CLS_CH, m - a0);
        __syncthreads();
        for (int idx = tid; idx < na * 64; idx += 256) {
            int r = idx >> 6, q = idx & 63;
            ((float4*)sa)[r * 64 + q] =
                ((const float4*)(g_e + (size_t)mem[a0 + r] * D_SZ))[q];
        }
        for (int b0 = 0; b0 < m; b0 += CLS_CH) {
            int nb = min(CLS_CH, m - b0);
            __syncthreads();
            for (int idx = tid; idx < nb * 64; idx += 256) {
                int r = idx >> 6, q = idx & 63;
                ((float4*)sb)[r * 64 + q] =
                    ((const float4*)(g_e + (size_t)mem[b0 + r] * D_SZ))[q];
            }
            __syncthreads();
            for (int p = tid; p < na * nb; p += 256) {
                int ar = p / nb, br = p % nb;
                if (a0 + ar == b0 + br) continue;
                const float4* ea = (const float4*)(sa + ar * D_SZ);
                const float4* eb = (const float4*)(sb + br * D_SZ);
                float s = 0.0f;
#pragma unroll 16
                for (int q = 0; q < D_SZ / 4; q++) {
                    float4 va = ea[q], vb = eb[q];
                    s = fmaf(va.x, vb.x, s); s = fmaf(va.y, vb.y, s);
                    s = fmaf(va.z, vb.z, s); s = fmaf(va.w, vb.w, s);
                }
                float d = fmaxf(1.0f - s, 0.0f);
                float hn = __uint_as_float(g_hn_bits[mem[a0 + ar]]);
                float loss = d - hn + MARGIN;
                if (loss > 0.0f) { lt += loss; lc++; }
            }
        }
    }
    __shared__ float st[256];
    __shared__ int   sc[256];
    st[tid] = lt; sc[tid] = lc;
    __syncthreads();
    for (int o = 128; o; o >>= 1) {
        if (tid < o) { st[tid] += st[tid + o]; sc[tid] += sc[tid + o]; }
        __syncthreads();
    }
    if (tid == 0 && sc[0] > 0) {
        atomicAdd(&g_total, st[0]);
        atomicAdd(&g_count, sc[0]);
    }
}

__global__ void finalize_k(float* out) {
    if (threadIdx.x == 0)
        out[0] = (g_count > 0) ? (g_total / (float)g_count) : 0.0f;
}

// ---------------- launch ----------------
extern "C" void kernel_launch(void* const* d_in, const int* in_sizes, int n_in,
                              void* d_out, int out_size) {
    const float* emb = (const float*)d_in[0];
    const int* labels = (const int*)d_in[1];
    float* out = (float*)d_out;
    (void)in_sizes; (void)n_in; (void)out_size;

    static int attr_set = 0;
    if (!attr_set) {
        cudaFuncSetAttribute(min_gemm_hmma,
                             cudaFuncAttributeMaxDynamicSharedMemorySize, SMEM_DYN);
        cudaFuncSetAttribute(class_loss_k,
                             cudaFuncAttributeMaxDynamicSharedMemorySize, CLS_SMEM);
        attr_set = 1;
    }

    pre_k<<<33, 256>>>(labels);
    normalize_k<<<B_SZ / 8, 256>>>(emb, labels);
    min_gemm_hmma<<<TM * (TM + 1) / 2, 256, SMEM_DYN>>>(labels);
    class_loss_k<<<NCLS, 256, CLS_SMEM>>>();
    finalize_k<<<1, 32>>>(out);
}

// round 5
// speedup vs baseline: 3.2486x; 1.4767x over previous
#include <cuda_runtime.h>
#include <cuda_fp16.h>
#include <cstdint>

#define B_SZ 8192
#define D_SZ 256
#define NCLS 512
#define MAXM 128
#define TM 64
#define MARGIN 1.0f
#define BIGF 1e9f

#define TILE_BYTES 16384                   // 128 rows * 128B
#define STAGE_BYTES (3 * TILE_BYTES)       // Ah, Bh, Bl
#define SMEM_DYN (2 * STAGE_BYTES + 1024)  // 97.25 KB -> 2 CTAs/SM
#define CLS_CH 32
#define CLS_SMEM (2 * CLS_CH * D_SZ * 4)   // 64KB

// ---------------- device scratch ----------------
__device__ float        g_e[B_SZ * D_SZ];
__device__ __half       g_hi[B_SZ * D_SZ];
__device__ __half       g_lo[B_SZ * D_SZ];
__device__ unsigned int g_hn_bits[B_SZ];
__device__ int          g_cls_cnt[NCLS];
__device__ int          g_cls_members[NCLS * MAXM];
__device__ float        g_total;
__device__ int          g_count;
__device__ int          g_lab64;

// ---------------- helpers ----------------
__device__ __forceinline__ uint32_t smem_u32(const void* p) {
    uint32_t a;
    asm("{ .reg .u64 t; cvta.to.shared.u64 t, %1; cvt.u32.u64 %0, t; }" : "=r"(a) : "l"(p));
    return a;
}
__device__ __forceinline__ int get_label(const int* l, int i, int is64) {
    return is64 ? l[2 * i] : l[i];
}

#define LDSM4(r0, r1, r2, r3, addr)                                              \
    asm volatile("ldmatrix.sync.aligned.m8n8.x4.shared.b16 {%0,%1,%2,%3}, [%4];" \
                 : "=r"(r0), "=r"(r1), "=r"(r2), "=r"(r3) : "r"(addr))

#define MMA16816(d, a0, a1, a2, a3, b0, b1)                                  \
    asm volatile("mma.sync.aligned.m16n8k16.row.col.f32.f16.f16.f32 "        \
                 "{%0,%1,%2,%3}, {%4,%5,%6,%7}, {%8,%9}, {%0,%1,%2,%3};"     \
                 : "+f"(d[0]), "+f"(d[1]), "+f"(d[2]), "+f"(d[3])            \
                 : "r"(a0), "r"(a1), "r"(a2), "r"(a3), "r"(b0), "r"(b1))

#define CPA16(dst, src)                                                       \
    asm volatile("cp.async.cg.shared.global [%0], [%1], 16;"                  \
                 :: "r"(dst), "l"(src) : "memory")
#define CPA_COMMIT asm volatile("cp.async.commit_group;" ::: "memory")
#define CPA_WAIT(n) asm volatile("cp.async.wait_group %0;" :: "n"(n) : "memory")

// ---------------- pre: detect label dtype + reset state ----------------
__global__ void pre_k(const int* __restrict__ labels) {
    if (blockIdx.x == 0) {
        __shared__ int sh[256];
        int acc = 0;
        for (int i = threadIdx.x; i < B_SZ / 2; i += 256) acc |= labels[2 * i + 1];
        sh[threadIdx.x] = acc;
        __syncthreads();
        for (int o = 128; o; o >>= 1) {
            if (threadIdx.x < o) sh[threadIdx.x] |= sh[threadIdx.x + o];
            __syncthreads();
        }
        if (threadIdx.x == 0) g_lab64 = (sh[0] == 0) ? 1 : 0;
    } else {
        int t = (blockIdx.x - 1) * 256 + threadIdx.x;
        if (t < B_SZ) g_hn_bits[t] = __float_as_uint(BIGF);
        if (t < NCLS) g_cls_cnt[t] = 0;
        if (t == 0) { g_total = 0.0f; g_count = 0; }
    }
}

// ---------------- normalize (warp/row) + fp16 split + class bucketing ----------------
__global__ __launch_bounds__(256) void normalize_k(const float* __restrict__ x,
                                                   const int* __restrict__ labels) {
    int wid = threadIdx.x >> 5, lane = threadIdx.x & 31;
    int row = blockIdx.x * 8 + wid;
    size_t base = (size_t)row * D_SZ + lane * 8;
    float4 v0 = *(const float4*)(x + base);
    float4 v1 = *(const float4*)(x + base + 4);
    float e[8] = {v0.x, v0.y, v0.z, v0.w, v1.x, v1.y, v1.z, v1.w};
    float s = 0.0f;
#pragma unroll
    for (int q = 0; q < 8; q++) s += e[q] * e[q];
#pragma unroll
    for (int o = 16; o; o >>= 1) s += __shfl_xor_sync(0xFFFFFFFFu, s, o);
    float inv = 1.0f / fmaxf(sqrtf(s), 1e-12f);

    union { __half h[8]; uint4 u; } hi, lo;
#pragma unroll
    for (int q = 0; q < 8; q++) {
        e[q] *= inv;
        __half h = __float2half_rn(e[q]);
        hi.h[q] = h;
        lo.h[q] = __float2half_rn(e[q] - __half2float(h));
    }
    *(float4*)(g_e + base)     = make_float4(e[0], e[1], e[2], e[3]);
    *(float4*)(g_e + base + 4) = make_float4(e[4], e[5], e[6], e[7]);
    *(uint4*)(g_hi + base) = hi.u;
    *(uint4*)(g_lo + base) = lo.u;

    if (lane == 0) {
        int c = get_label(labels, row, g_lab64);
        int p = atomicAdd(&g_cls_cnt[c], 1);
        if (p < MAXM) g_cls_members[c * MAXM + p] = row;
    }
}

// ---------------- HMMA GEMM + masked min: 3-tile stages, 2 CTAs/SM ----------------
__device__ __forceinline__ void issue_chunk(uint32_t sbase, int chunk, int ib, int jb,
                                            int tid) {
#pragma unroll
    for (int r = 0; r < 4; r++) {
        int idx = tid + 256 * r;             // 0..1023
        int row = idx >> 3, seg = idx & 7;
        size_t gofs = (size_t)row * 512 + (size_t)chunk * 128 + (size_t)seg * 16;
        uint32_t off = (uint32_t)(row * 128 + ((seg * 16) ^ ((row & 7) << 4)));
        CPA16(sbase + 0 * TILE_BYTES + off, (const char*)g_hi + (size_t)ib * 512 + gofs);
        CPA16(sbase + 1 * TILE_BYTES + off, (const char*)g_hi + (size_t)jb * 512 + gofs);
        CPA16(sbase + 2 * TILE_BYTES + off, (const char*)g_lo + (size_t)jb * 512 + gofs);
    }
    CPA_COMMIT;
}

__global__ __launch_bounds__(256, 2) void min_gemm_hmma(const int* __restrict__ labels) {
    extern __shared__ char dyn[];
    __shared__ int   labA[128], labB[128];
    __shared__ float s_rmin[128][4];
    __shared__ float s_cmin[128][2];

    int bid = blockIdx.x;
    int bi = 0;
    while (((bi + 1) * (2 * TM - bi)) / 2 <= bid) bi++;
    int bj = bi + (bid - (bi * (2 * TM - bi + 1)) / 2);
    int ib = bi * 128, jb = bj * 128;

    int tid = threadIdx.x;
    int lane = tid & 31, wid = tid >> 5;
    int wr = wid >> 2, wc = wid & 3;
    int rbase = wr * 64, cbase = wc * 32;
    int is64 = g_lab64;

    uint32_t dbase = smem_u32(dyn);
    uint32_t tb = (dbase + 1023u) & ~1023u;

    if (tid < 128) labA[tid] = get_label(labels, ib + tid, is64);
    else           labB[tid - 128] = get_label(labels, jb + (tid - 128), is64);

    issue_chunk(tb, 0, ib, jb, tid);

    float acc[4][4][4];
#pragma unroll
    for (int mf = 0; mf < 4; mf++)
#pragma unroll
        for (int nf = 0; nf < 4; nf++)
#pragma unroll
            for (int r = 0; r < 4; r++) acc[mf][nf][r] = 0.0f;

    int a_row = lane & 15;
    int a_kb  = (lane >> 4) * 16;
    uint32_t a_xor = (uint32_t)(a_row & 7) << 4;
    int b_n  = (lane & 7) + ((lane >> 4) << 3);
    int b_kb = ((lane >> 3) & 1) * 16;
    uint32_t b_xor = (uint32_t)(b_n & 7) << 4;
    uint32_t aOff = (uint32_t)(rbase + a_row) * 128;
    uint32_t bOff0 = (uint32_t)(cbase + b_n) * 128;
    uint32_t bOff1 = bOff0 + 16 * 128;

    for (int chunk = 0; chunk < 4; chunk++) {
        if (chunk < 3) {
            issue_chunk(tb + ((chunk + 1) & 1) * STAGE_BYTES, chunk + 1, ib, jb, tid);
            CPA_WAIT(1);
        } else {
            CPA_WAIT(0);
        }
        __syncthreads();

        uint32_t base = tb + (chunk & 1) * STAGE_BYTES;
        uint32_t tAh = base;
        uint32_t tBh = base + TILE_BYTES, tBl = base + 2 * TILE_BYTES;

#pragma unroll
        for (int ks = 0; ks < 4; ks++) {
            uint32_t kA = ((uint32_t)(ks * 32 + a_kb)) ^ a_xor;
            uint32_t kB = ((uint32_t)(ks * 32 + b_kb)) ^ b_xor;
            uint32_t bh[8], bl[8];
            LDSM4(bh[0], bh[1], bh[2], bh[3], tBh + bOff0 + kB);
            LDSM4(bh[4], bh[5], bh[6], bh[7], tBh + bOff1 + kB);
            LDSM4(bl[0], bl[1], bl[2], bl[3], tBl + bOff0 + kB);
            LDSM4(bl[4], bl[5], bl[6], bl[7], tBl + bOff1 + kB);
#pragma unroll
            for (int mf = 0; mf < 4; mf++) {
                uint32_t ah0, ah1, ah2, ah3;
                LDSM4(ah0, ah1, ah2, ah3, tAh + aOff + mf * 2048 + kA);
                MMA16816(acc[mf][0], ah0, ah1, ah2, ah3, bh[0], bh[1]);
                MMA16816(acc[mf][1], ah0, ah1, ah2, ah3, bh[2], bh[3]);
                MMA16816(acc[mf][2], ah0, ah1, ah2, ah3, bh[4], bh[5]);
                MMA16816(acc[mf][3], ah0, ah1, ah2, ah3, bh[6], bh[7]);
                MMA16816(acc[mf][0], ah0, ah1, ah2, ah3, bl[0], bl[1]);
                MMA16816(acc[mf][1], ah0, ah1, ah2, ah3, bl[2], bl[3]);
                MMA16816(acc[mf][2], ah0, ah1, ah2, ah3, bl[4], bl[5]);
                MMA16816(acc[mf][3], ah0, ah1, ah2, ah3, bl[6], bl[7]);
            }
        }
        __syncthreads();
    }

    // ---------------- epilogue: mask + min in registers ----------------
    int qr = lane >> 2, qc = lane & 3;
    float rmin[8], cmin[8];
#pragma unroll
    for (int i = 0; i < 8; i++) { rmin[i] = BIGF; cmin[i] = BIGF; }

#pragma unroll
    for (int mf = 0; mf < 4; mf++) {
        int la0 = labA[rbase + mf * 16 + qr];
        int la1 = labA[rbase + mf * 16 + qr + 8];
#pragma unroll
        for (int nf = 0; nf < 4; nf++) {
            int c0 = cbase + nf * 8 + qc * 2;
            int lb0 = labB[c0], lb1 = labB[c0 + 1];
            float d0 = fmaxf(1.0f - acc[mf][nf][0], 0.0f);
            float d1 = fmaxf(1.0f - acc[mf][nf][1], 0.0f);
            float d2 = fmaxf(1.0f - acc[mf][nf][2], 0.0f);
            float d3 = fmaxf(1.0f - acc[mf][nf][3], 0.0f);
            float v0 = (la0 != lb0) ? d0 : BIGF;
            float v1 = (la0 != lb1) ? d1 : BIGF;
            float v2 = (la1 != lb0) ? d2 : BIGF;
            float v3 = (la1 != lb1) ? d3 : BIGF;
            rmin[mf * 2 + 0] = fminf(rmin[mf * 2 + 0], fminf(v0, v1));
            rmin[mf * 2 + 1] = fminf(rmin[mf * 2 + 1], fminf(v2, v3));
            cmin[nf * 2 + 0] = fminf(cmin[nf * 2 + 0], fminf(v0, v2));
            cmin[nf * 2 + 1] = fminf(cmin[nf * 2 + 1], fminf(v1, v3));
        }
    }
#pragma unroll
    for (int o = 1; o <= 2; o <<= 1)
#pragma unroll
        for (int i = 0; i < 8; i++)
            rmin[i] = fminf(rmin[i], __shfl_xor_sync(0xFFFFFFFFu, rmin[i], o));
    if (qc == 0) {
#pragma unroll
        for (int mf = 0; mf < 4; mf++) {
            s_rmin[rbase + mf * 16 + qr + 0][wc] = rmin[mf * 2 + 0];
            s_rmin[rbase + mf * 16 + qr + 8][wc] = rmin[mf * 2 + 1];
        }
    }
#pragma unroll
    for (int o = 4; o <= 16; o <<= 1)
#pragma unroll
        for (int i = 0; i < 8; i++)
            cmin[i] = fminf(cmin[i], __shfl_xor_sync(0xFFFFFFFFu, cmin[i], o));
    if (lane < 4) {
#pragma unroll
        for (int nf = 0; nf < 4; nf++) {
            s_cmin[cbase + nf * 8 + lane * 2 + 0][wr] = cmin[nf * 2 + 0];
            s_cmin[cbase + nf * 8 + lane * 2 + 1][wr] = cmin[nf * 2 + 1];
        }
    }
    __syncthreads();
    if (tid < 128) {
        float m = fminf(fminf(s_rmin[tid][0], s_rmin[tid][1]),
                        fminf(s_rmin[tid][2], s_rmin[tid][3]));
        if (m < BIGF) atomicMin(&g_hn_bits[ib + tid], __float_as_uint(m));
        float c = fminf(s_cmin[tid][0], s_cmin[tid][1]);
        if (c < BIGF) atomicMin(&g_hn_bits[jb + tid], __float_as_uint(c));
    }
}

// ---------------- positive-pair losses: warp-per-pair, smem-cached ----------------
__global__ __launch_bounds__(256) void class_loss_k() {
    extern __shared__ float cls[];
    float* sa = cls;
    float* sb = cls + CLS_CH * D_SZ;
    int c = blockIdx.x;
    int m = min(g_cls_cnt[c], MAXM);
    int tid = threadIdx.x;
    int wid = tid >> 5, lane = tid & 31;
    const int* mem = &g_cls_members[c * MAXM];
    float lt = 0.0f; int lc = 0;

    for (int a0 = 0; a0 < m; a0 += CLS_CH) {
        int na = min(CLS_CH, m - a0);
        __syncthreads();
        for (int idx = tid; idx < na * 64; idx += 256)
            ((float4*)sa)[idx] = ((const float4*)(g_e + (size_t)mem[a0 + idx / 64] * D_SZ))[idx & 63];
        for (int b0 = 0; b0 < m; b0 += CLS_CH) {
            int nb = min(CLS_CH, m - b0);
            __syncthreads();
            for (int idx = tid; idx < nb * 64; idx += 256)
                ((float4*)sb)[idx] = ((const float4*)(g_e + (size_t)mem[b0 + idx / 64] * D_SZ))[idx & 63];
            __syncthreads();
            // warp per pair: lanes split D (8 floats each), shfl reduce
            for (int p = wid; p < na * nb; p += 8) {
                int ar = p / nb, br = p % nb;
                if (a0 + ar == b0 + br) continue;
                const float4* ea = (const float4*)(sa + ar * D_SZ) + lane * 2;
                const float4* eb = (const float4*)(sb + br * D_SZ) + lane * 2;
                float4 va0 = ea[0], va1 = ea[1], vb0 = eb[0], vb1 = eb[1];
                float s = va0.x * vb0.x + va0.y * vb0.y + va0.z * vb0.z + va0.w * vb0.w
                        + va1.x * vb1.x + va1.y * vb1.y + va1.z * vb1.z + va1.w * vb1.w;
#pragma unroll
                for (int o = 16; o; o >>= 1) s += __shfl_xor_sync(0xFFFFFFFFu, s, o);
                if (lane == 0) {
                    float d = fmaxf(1.0f - s, 0.0f);
                    float hn = __uint_as_float(g_hn_bits[mem[a0 + ar]]);
                    float loss = d - hn + MARGIN;
                    if (loss > 0.0f) { lt += loss; lc++; }
                }
            }
        }
    }
    __shared__ float st[256];
    __shared__ int   sc[256];
    st[tid] = lt; sc[tid] = lc;
    __syncthreads();
    for (int o = 128; o; o >>= 1) {
        if (tid < o) { st[tid] += st[tid + o]; sc[tid] += sc[tid + o]; }
        __syncthreads();
    }
    if (tid == 0 && sc[0] > 0) {
        atomicAdd(&g_total, st[0]);
        atomicAdd(&g_count, sc[0]);
    }
}

__global__ void finalize_k(float* out) {
    if (threadIdx.x == 0)
        out[0] = (g_count > 0) ? (g_total / (float)g_count) : 0.0f;
}

// ---------------- launch ----------------
extern "C" void kernel_launch(void* const* d_in, const int* in_sizes, int n_in,
                              void* d_out, int out_size) {
    const float* emb = (const float*)d_in[0];
    const int* labels = (const int*)d_in[1];
    float* out = (float*)d_out;
    (void)in_sizes; (void)n_in; (void)out_size;

    static int attr_set = 0;
    if (!attr_set) {
        cudaFuncSetAttribute(min_gemm_hmma,
                             cudaFuncAttributeMaxDynamicSharedMemorySize, SMEM_DYN);
        cudaFuncSetAttribute(class_loss_k,
                             cudaFuncAttributeMaxDynamicSharedMemorySize, CLS_SMEM);
        attr_set = 1;
    }

    pre_k<<<33, 256>>>(labels);
    normalize_k<<<B_SZ / 8, 256>>>(emb, labels);
    min_gemm_hmma<<<TM * (TM + 1) / 2, 256, SMEM_DYN>>>(labels);
    class_loss_k<<<NCLS, 256, CLS_SMEM>>>();
    finalize_k<<<1, 32>>>(out);
}